// round 4
// baseline (speedup 1.0000x reference)
#include <cuda_runtime.h>
#include <math.h>

#define N_IN 12288
#define H0 256
#define H1 32
#define H2 32
#define NB 8192
#define ROWS_PER_CTA 8
#define THREADS 256
#define F4T 12            // float4 chunks per thread per row (12288/4/256)
#define MAX_NNZ 256       // per row-side index-list capacity (mean ~31, 12-sigma safe)

// Transposed feature-transform weights: column j is 256 contiguous floats.
// __device__ global scratch (allocation-free per harness rules). 12.6 MB, L2-resident.
__device__ float g_ftT[N_IN * H0];

// side-encoding mode: 0 = int32, 1 = packed uint8, 2 = float32
__device__ int g_side_mode;

__global__ void detect_side_mode(const unsigned int* __restrict__ side_words) {
    // Inspect first 2048 words (8 KB) — safe under any of the 3 encodings
    // (uint8 -> 8 KB total; int32/f32 -> 32 KB total).
    __shared__ int has_float, has_big;
    if (threadIdx.x == 0) { has_float = 0; has_big = 0; }
    __syncthreads();
    for (int i = threadIdx.x; i < 2048; i += blockDim.x) {
        unsigned int v = side_words[i];
        if (v == 0x3f800000u) atomicOr(&has_float, 1);   // 1.0f bit pattern
        else if (v > 1u) atomicOr(&has_big, 1);          // packed 0/1 bytes
    }
    __syncthreads();
    if (threadIdx.x == 0)
        g_side_mode = has_float ? 2 : (has_big ? 1 : 0);
}

__global__ void transpose_ft(const float* __restrict__ ftw) {
    __shared__ float tile[32][33];
    int j0 = blockIdx.x * 32;   // N_IN
    int h0 = blockIdx.y * 32;   // H0
    int tx = threadIdx.x, ty = threadIdx.y;
#pragma unroll
    for (int r = 0; r < 32; r += 8)
        tile[ty + r][tx] = ftw[(size_t)(h0 + ty + r) * N_IN + j0 + tx];
    __syncthreads();
#pragma unroll
    for (int r = 0; r < 32; r += 8)
        g_ftT[(size_t)(j0 + ty + r) * H0 + h0 + tx] = tile[tx][ty + r];
}

struct Smem {
    float l1w[H1 * 2 * H0];        // 64 KB, staged once per CTA
    float l2w[H2 * (H1 + 1)];      // padded stride 33 -> conflict-free
    float l3w[H2];
    float ftb[H0];
    float l1b[H1];
    float l2b[H2];
    float l3b;
    float o0[2 * H0];
    float o1[H1];
    unsigned short wlist[MAX_NNZ];
    unsigned short blist[MAX_NNZ];
    int wsum[8];
};

__device__ __forceinline__ float clamp01(float x) { return fminf(fmaxf(x, 0.f), 1.f); }

__device__ __forceinline__ bool read_side(const void* side, int row, int mode) {
    if (mode == 0) return ((const int*)side)[row] != 0;
    if (mode == 1) return ((const unsigned char*)side)[row] != 0;
    return ((const float*)side)[row] != 0.0f;
}

// Deterministic sparse scan: per-thread stash + block prefix sum gives a fixed
// list order (wid, lane, i) independent of timing -> bit-reproducible sums.
__device__ __forceinline__ int scan_row(const uint4* __restrict__ rowp, int t,
                                        unsigned short* list, int* wsum) {
    unsigned short loc[F4T * 4];
    int cnt = 0;
#pragma unroll
    for (int i = 0; i < F4T; i++) {
        int p = i * THREADS + t;          // coalesced strided float4 scan
        uint4 v = rowp[p];
        if (v.x | v.y | v.z | v.w) {      // fast path: ~96% of chunks all-zero
            int base = p * 4;
            if (v.x) loc[cnt++] = (unsigned short)base;
            if (v.y) loc[cnt++] = (unsigned short)(base + 1);
            if (v.z) loc[cnt++] = (unsigned short)(base + 2);
            if (v.w) loc[cnt++] = (unsigned short)(base + 3);
        }
    }
    int lane = t & 31, wid = t >> 5;
    int inc = cnt;
#pragma unroll
    for (int off = 1; off < 32; off <<= 1) {
        int n = __shfl_up_sync(0xffffffffu, inc, off);
        if (lane >= off) inc += n;
    }
    if (lane == 31) wsum[wid] = inc;
    __syncthreads();
    if (wid == 0) {
        int v = (lane < 8) ? wsum[lane] : 0;
#pragma unroll
        for (int off = 1; off < 8; off <<= 1) {
            int n = __shfl_up_sync(0xffffffffu, v, off);
            if (lane >= off) v += n;
        }
        if (lane < 8) wsum[lane] = v;     // inclusive warp totals
    }
    __syncthreads();
    int base = (wid ? wsum[wid - 1] : 0) + inc - cnt;
    int total = min(wsum[7], MAX_NNZ);
    for (int k = 0; k < cnt; k++) {
        int pos = base + k;
        if (pos < MAX_NNZ) list[pos] = loc[k];
    }
    __syncthreads();                       // list visible; wsum reusable
    return total;
}

// Gather-accumulate ft_w^T columns; 4 partial sums for L2 MLP, fixed fp order.
__device__ __forceinline__ float accum_cols(const unsigned short* list, int n, int t) {
    float s0 = 0.f, s1 = 0.f, s2 = 0.f, s3 = 0.f;
    int i = 0;
    for (; i + 4 <= n; i += 4) {
        s0 += g_ftT[(int)list[i]     * H0 + t];
        s1 += g_ftT[(int)list[i + 1] * H0 + t];
        s2 += g_ftT[(int)list[i + 2] * H0 + t];
        s3 += g_ftT[(int)list[i + 3] * H0 + t];
    }
    for (; i < n; i++) s0 += g_ftT[(int)list[i] * H0 + t];
    return (s0 + s1) + (s2 + s3);
}

__global__ __launch_bounds__(THREADS) void nnue_kernel(
    const float* __restrict__ wf, const float* __restrict__ bf,
    const void* __restrict__ side,
    const float* __restrict__ ftb,
    const float* __restrict__ l1w, const float* __restrict__ l1b,
    const float* __restrict__ l2w, const float* __restrict__ l2b,
    const float* __restrict__ l3w, const float* __restrict__ l3b,
    float* __restrict__ out)
{
    extern __shared__ unsigned char smem_raw[];
    Smem* S = (Smem*)smem_raw;
    int t = threadIdx.x;
    int lane = t & 31, wid = t >> 5;
    int side_mode = g_side_mode;

    // Stage small weights into SMEM once per CTA (amortized over 8 rows).
    {
        const float4* src = (const float4*)l1w;
        float4* dst = (float4*)S->l1w;
        for (int i = t; i < H1 * 2 * H0 / 4; i += THREADS) dst[i] = src[i];
        for (int i = t; i < H2 * H1; i += THREADS)
            S->l2w[(i >> 5) * (H1 + 1) + (i & 31)] = l2w[i];
        if (t < H2) S->l3w[t] = l3w[t];
        S->ftb[t] = ftb[t];
        if (t < H1) S->l1b[t] = l1b[t];
        if (t < H2) S->l2b[t] = l2b[t];
        if (t == 0) S->l3b = l3b[0];
    }
    __syncthreads();

    for (int r = 0; r < ROWS_PER_CTA; r++) {
        int row = blockIdx.x * ROWS_PER_CTA + r;
        const uint4* wrow = (const uint4*)(wf + (size_t)row * N_IN);
        const uint4* brow = (const uint4*)(bf + (size_t)row * N_IN);
        int wn = scan_row(wrow, t, S->wlist, S->wsum);
        int bn = scan_row(brow, t, S->blist, S->wsum);

        float aw = S->ftb[t] + accum_cols(S->wlist, wn, t);
        float ab = S->ftb[t] + accum_cols(S->blist, bn, t);
        bool sd = read_side(side, row, side_mode);
        S->o0[t]      = clamp01(sd ? aw : ab);
        S->o0[H0 + t] = clamp01(sd ? ab : aw);
        __syncthreads();

        // l1: warp `wid` computes outputs 4*wid..4*wid+3; lane-consecutive SMEM
        // reads (conflict-free), shfl-xor reduction (deterministic tree).
#pragma unroll
        for (int oo = 0; oo < 4; oo++) {
            int o = wid * 4 + oo;
            float s = 0.f;
            const float* wrowp = &S->l1w[o * 2 * H0];
#pragma unroll
            for (int j = 0; j < 2 * H0 / 32; j++) {
                int k = j * 32 + lane;
                s += wrowp[k] * S->o0[k];
            }
#pragma unroll
            for (int off = 16; off; off >>= 1) s += __shfl_xor_sync(0xffffffffu, s, off);
            if (lane == 0) S->o1[o] = clamp01(s + S->l1b[o]);
        }
        __syncthreads();

        if (wid == 0) {
            // l2: lane = output; padded stride 33 -> lane-distinct banks.
            float s = 0.f;
#pragma unroll
            for (int k = 0; k < H1; k++)
                s += S->l2w[lane * (H1 + 1) + k] * S->o1[k];
            float v = clamp01(s + S->l2b[lane]) * S->l3w[lane];   // fused l3 mul
#pragma unroll
            for (int off = 16; off; off >>= 1) v += __shfl_xor_sync(0xffffffffu, v, off);
            if (lane == 0) {
                float x = (v + S->l3b) * 1.5f;   // OUTPUT_SCALE / WDL_SCALE = 300/200
                out[row] = 1.f / (1.f + expf(-x));
            }
        }
        __syncthreads();
    }
}

extern "C" void kernel_launch(void* const* d_in, const int* in_sizes, int n_in,
                              void* d_out, int out_size) {
    const float* wf  = (const float*)d_in[0];
    const float* bf  = (const float*)d_in[1];
    const void*  side = d_in[2];
    const float* ftw = (const float*)d_in[3];
    const float* ftb = (const float*)d_in[4];
    const float* l1w = (const float*)d_in[5];
    const float* l1b = (const float*)d_in[6];
    const float* l2w = (const float*)d_in[7];
    const float* l2b = (const float*)d_in[8];
    const float* l3w = (const float*)d_in[9];
    const float* l3b = (const float*)d_in[10];
    float* out = (float*)d_out;

    cudaFuncSetAttribute(nnue_kernel, cudaFuncAttributeMaxDynamicSharedMemorySize,
                         (int)sizeof(Smem));

    detect_side_mode<<<1, 256>>>((const unsigned int*)side);
    transpose_ft<<<dim3(N_IN / 32, H0 / 32), dim3(32, 8)>>>(ftw);
    nnue_kernel<<<NB / ROWS_PER_CTA, THREADS, sizeof(Smem)>>>(
        wf, bf, side, ftb, l1w, l1b, l2w, l2b, l3w, l3b, out);
}